// round 8
// baseline (speedup 1.0000x reference)
#include <cuda_runtime.h>

// ContrastiveTreeLoss, single-launch, delta formulation (v3).
//
// Shapes (fixed by the problem instance):
//   arc_scores [B=512, N=256, N=256] f32
//   gold_heads [B, N] i32
//   mask       [B, N] i32
//   neg_heads  [K=4, B, N] i32
//   out        scalar f32 = mean_{k,b} relu(MARGIN - gold_total[b] + neg_total[k,b])
//
// Key insight (v3): the loss depends only on neg_total - gold_total, and each
// negative tree differs from gold at <=2 dependents (one head swap). So:
//   margin - gold + neg_k = margin + sum_{d: nh!=gh} mask[d]*(arc[b,nh,d]-arc[b,gh,d])
// This removes the 130K-point random gather of gold scores (the measured DRAM
// bottleneck: ~16MB of random line fills) entirely. Remaining traffic is ~3MB
// of coalesced index streams + ~8K scattered loads chip-wide.

#define TL_B 512
#define TL_N 256
#define TL_K 4
#define TL_MARGIN 2.0f

__device__ float g_partial[TL_B];
__device__ unsigned int g_done_count;   // zero-init; reset each launch by last CTA

__global__ __launch_bounds__(TL_N, 4)
void tree_loss_delta_kernel(const float* __restrict__ arc,
                            const int*   __restrict__ gold,
                            const int*   __restrict__ mask,
                            const int*   __restrict__ neg,
                            float*       __restrict__ out)
{
    const int b = blockIdx.x;     // sentence
    const int d = threadIdx.x;    // dependent index 0..N-1 (d=0 unused)
    const float* __restrict__ arcb = arc + (size_t)b * TL_N * TL_N;

    float vals[TL_K];             // per-thread delta contribution for each negative
#pragma unroll
    for (int k = 0; k < TL_K; k++) vals[k] = 0.0f;

    if (d >= 1) {
        const float m = (float)__ldg(&mask[b * TL_N + d]);
        int gh = __ldg(&gold[b * TL_N + d]);
        gh = min(max(gh, 0), TL_N - 1);
#pragma unroll
        for (int k = 0; k < TL_K; k++) {
            int nh = __ldg(&neg[((size_t)k * TL_B + b) * TL_N + d]);
            nh = min(max(nh, 0), TL_N - 1);
            if (nh != gh) {
                // Rare path: <=2 lanes per (k,b). Two scattered loads, fully
                // predicated off on all other lanes (no wavefronts, no traffic).
                const float av = __ldg(arcb + nh * TL_N + d);
                const float gv = __ldg(arcb + gh * TL_N + d);
                vals[k] = (av - gv) * m;
            }
        }
    }

    // 4-way block reduction: warp shuffle -> 8 warp-partials in smem -> warp 0
    __shared__ float sh[8][TL_K];
    const int lane = d & 31;
    const int warp = d >> 5;
#pragma unroll
    for (int k = 0; k < TL_K; k++) {
        float v = vals[k];
#pragma unroll
        for (int off = 16; off > 0; off >>= 1)
            v += __shfl_down_sync(0xffffffffu, v, off);
        if (lane == 0) sh[warp][k] = v;
    }
    __syncthreads();

    __shared__ bool is_last;
    if (d < 32) {
#pragma unroll
        for (int k = 0; k < TL_K; k++) {
            float v = (d < 8) ? sh[d][k] : 0.0f;
#pragma unroll
            for (int off = 4; off > 0; off >>= 1)
                v += __shfl_down_sync(0xffffffffu, v, off);
            vals[k] = v;   // lane 0 holds delta_k = neg_total_k - gold_total
        }
        if (d == 0) {
            float loss = 0.0f;
#pragma unroll
            for (int k = 0; k < TL_K; k++)
                loss += fmaxf(TL_MARGIN + vals[k], 0.0f);
            g_partial[b] = loss;
            __threadfence();   // release: order the store before the atomic
            unsigned int prev = atomicAdd(&g_done_count, 1u);
            is_last = (prev == (unsigned int)(TL_B - 1));
        }
    }
    __syncthreads();

    if (is_last) {
        if (d == 0) __threadfence();   // acquire: see all writers' stores
        __syncthreads();
        // 256 threads reduce 512 per-sentence losses (all in L2 by now).
        float v = g_partial[d] + g_partial[d + TL_N];
        __shared__ float rsh[8];
#pragma unroll
        for (int off = 16; off > 0; off >>= 1)
            v += __shfl_down_sync(0xffffffffu, v, off);
        if (lane == 0) rsh[warp] = v;
        __syncthreads();
        if (d < 32) {
            float w = (d < 8) ? rsh[d] : 0.0f;
#pragma unroll
            for (int off = 4; off > 0; off >>= 1)
                w += __shfl_down_sync(0xffffffffu, w, off);
            if (d == 0) {
                out[0] = w * (1.0f / (float)(TL_K * TL_B));
                atomicExch(&g_done_count, 0u);   // reset for next graph replay
            }
        }
    }
}

extern "C" void kernel_launch(void* const* d_in, const int* in_sizes, int n_in,
                              void* d_out, int out_size)
{
    const float* arc  = (const float*)d_in[0];  // arc_scores [B,N,N]
    const int*   gold = (const int*)  d_in[1];  // gold_heads [B,N]
    const int*   mask = (const int*)  d_in[2];  // mask       [B,N]
    const int*   neg  = (const int*)  d_in[3];  // neg_heads  [K,B,N]
    (void)in_sizes; (void)n_in; (void)out_size;

    tree_loss_delta_kernel<<<TL_B, TL_N>>>(arc, gold, mask, neg, (float*)d_out);
}

// round 9
// speedup vs baseline: 1.0295x; 1.0295x over previous
#include <cuda_runtime.h>

// ContrastiveTreeLoss, single-launch, delta formulation, warp-per-sentence (v4).
//
// Shapes (fixed by the problem instance):
//   arc_scores [B=512, N=256, N=256] f32
//   gold_heads [B, N] i32
//   mask       [B, N] i32
//   neg_heads  [K=4, B, N] i32
//   out        scalar f32 = mean_{k,b} relu(MARGIN - gold_total[b] + neg_total[k,b])
//
// v3 insight (kept): loss depends only on neg_total - gold_total and each
// negative differs from gold at <=2 dependents:
//   margin - gold + neg_k = margin + sum_{d: nh!=gh} mask[d]*(arc[b,nh,d]-arc[b,gh,d])
//
// v4 changes (targets the post-traffic bottleneck: arrival/atomic tail and
// LDG issue count):
//  * one WARP per sentence, 8 warps/CTA -> grid of 64 CTAs. Global arrival
//    count drops 512 -> 64 (contended same-address atomics serialized ~8x less,
//    straggler tail shorter).
//  * int4 vectorized index loads: 12 x LDG.128 per lane per sentence instead
//    of 48 scalar LDGs.

#define TL_B 512
#define TL_N 256
#define TL_K 4
#define TL_MARGIN 2.0f
#define TL_WARPS 8
#define TL_GRID (TL_B / TL_WARPS)   // 64 CTAs

__device__ float g_partial[TL_GRID];
__device__ unsigned int g_done_count;   // zero-init; reset each launch by last CTA

__global__ __launch_bounds__(TL_WARPS * 32, 4)
void tree_loss_v4_kernel(const float* __restrict__ arc,
                         const int*   __restrict__ gold,
                         const int*   __restrict__ mask,
                         const int*   __restrict__ neg,
                         float*       __restrict__ out)
{
    const int lane = threadIdx.x & 31;
    const int warp = threadIdx.x >> 5;
    const int b    = blockIdx.x * TL_WARPS + warp;       // sentence for this warp

    const float* __restrict__ arcb  = arc + (size_t)b * TL_N * TL_N;
    const int4*  __restrict__ gold4 = (const int4*)(gold + b * TL_N);
    const int4*  __restrict__ mask4 = (const int4*)(mask + b * TL_N);

    float dk[TL_K] = {0.0f, 0.0f, 0.0f, 0.0f};          // delta_k partials

#pragma unroll
    for (int i = 0; i < TL_N / (32 * 4); i++) {          // 2 iterations
        const int idx = i * 32 + lane;                   // int4 index in the row
        const int d0  = idx * 4;                         // first dependent of this int4
        const int4 g4 = __ldg(gold4 + idx);
        const int4 m4 = __ldg(mask4 + idx);
        const int   gh[4] = {g4.x, g4.y, g4.z, g4.w};
        const float mm[4] = {(float)m4.x, (float)m4.y, (float)m4.z, (float)m4.w};

#pragma unroll
        for (int k = 0; k < TL_K; k++) {
            const int4* __restrict__ neg4 =
                (const int4*)(neg + ((size_t)k * TL_B + b) * TL_N);
            const int4 n4 = __ldg(neg4 + idx);
            const int nh[4] = {n4.x, n4.y, n4.z, n4.w};
#pragma unroll
            for (int j = 0; j < 4; j++) {
                const int d = d0 + j;
                if (d >= 1) {                            // dependent 0 excluded
                    int g = min(max(gh[j], 0), TL_N - 1);
                    int n = min(max(nh[j], 0), TL_N - 1);
                    if (n != g) {
                        // Rare path: <=2 lanes per (k, sentence). Two scattered
                        // loads, predicated off everywhere else.
                        dk[k] += (__ldg(arcb + n * TL_N + d) -
                                  __ldg(arcb + g * TL_N + d)) * mm[j];
                    }
                }
            }
        }
    }

    // Warp-reduce the 4 deltas; lane 0 forms the per-sentence loss.
#pragma unroll
    for (int k = 0; k < TL_K; k++) {
#pragma unroll
        for (int off = 16; off > 0; off >>= 1)
            dk[k] += __shfl_down_sync(0xffffffffu, dk[k], off);
    }

    __shared__ float wloss[TL_WARPS];
    if (lane == 0) {
        float loss = 0.0f;
#pragma unroll
        for (int k = 0; k < TL_K; k++)
            loss += fmaxf(TL_MARGIN + dk[k], 0.0f);
        wloss[warp] = loss;
    }
    __syncthreads();

    __shared__ bool is_last;
    if (threadIdx.x == 0) {
        float s = 0.0f;
#pragma unroll
        for (int w = 0; w < TL_WARPS; w++) s += wloss[w];
        g_partial[blockIdx.x] = s;
        __threadfence();                                 // release before the arrival
        unsigned int prev = atomicAdd(&g_done_count, 1u);
        is_last = (prev == (unsigned int)(TL_GRID - 1));
    }
    __syncthreads();

    if (is_last) {
        if (threadIdx.x == 0) __threadfence();           // acquire all writers
        __syncthreads();
        // Reduce 64 partials with 2 warps.
        float v = (threadIdx.x < TL_GRID) ? g_partial[threadIdx.x] : 0.0f;
        __shared__ float rsh[2];
        if (threadIdx.x < TL_GRID) {
#pragma unroll
            for (int off = 16; off > 0; off >>= 1)
                v += __shfl_down_sync(0xffffffffu, v, off);
            if (lane == 0) rsh[warp] = v;
        }
        __syncthreads();
        if (threadIdx.x == 0) {
            out[0] = (rsh[0] + rsh[1]) * (1.0f / (float)(TL_K * TL_B));
            atomicExch(&g_done_count, 0u);               // reset for next replay
        }
    }
}

extern "C" void kernel_launch(void* const* d_in, const int* in_sizes, int n_in,
                              void* d_out, int out_size)
{
    const float* arc  = (const float*)d_in[0];  // arc_scores [B,N,N]
    const int*   gold = (const int*)  d_in[1];  // gold_heads [B,N]
    const int*   mask = (const int*)  d_in[2];  // mask       [B,N]
    const int*   neg  = (const int*)  d_in[3];  // neg_heads  [K,B,N]
    (void)in_sizes; (void)n_in; (void)out_size;

    tree_loss_v4_kernel<<<TL_GRID, TL_WARPS * 32>>>(arc, gold, mask, neg, (float*)d_out);
}